// round 1
// baseline (speedup 1.0000x reference)
#include <cuda_runtime.h>

#define E_DIM 4096
#define N_DIM 8192
#define FIN   256
#define HEADS 8
#define DOUT  64
#define HD    512      // HEADS*DOUT
#define BATCH 2
#define LRELU_ALPHA 0.2f
#define NSLICE 16

// ---------------- scratch (allocation-free: __device__ globals) ----------------
__device__ float g_Wh[BATCH * N_DIM * HD];                 // (b,n,h,d)   33.5 MB
__device__ float g_av[BATCH * N_DIM * HEADS];              // (b,n,h)
__device__ float g_part[NSLICE * BATCH * E_DIM * HEADS];   // sliced logits partials
__device__ float g_ae[BATCH * E_DIM * HEADS];              // softmaxed edge attention
__device__ float g_m2[BATCH * E_DIM * HD];                 // ae-scaled edge features

// ---------------- generic 128x128x8 SGEMM, 8x8 per thread ----------------
// TRANSA=false: A is M x K row-major (lda = row stride)
// TRANSA=true : logical A[m,k] = Araw[k*lda + m]  (used for H^T)
// EPI=true    : C[m, col] *= ae[m*HEADS + col/DOUT]
template<bool TRANSA, bool EPI>
__global__ __launch_bounds__(256) void sgemm128(
    const float* __restrict__ A, const float* __restrict__ B, float* __restrict__ C,
    int M, int N, int K, int lda, int ldb, int ldc,
    long strideA, long strideB, long strideC,
    const float* __restrict__ ae, long strideAe)
{
    __shared__ float As[8][128];
    __shared__ float Bs[8][128];

    const int b = blockIdx.z;
    A += (long)b * strideA;
    B += (long)b * strideB;
    C += (long)b * strideC;
    const float* aeb = EPI ? (ae + (long)b * strideAe) : nullptr;

    const int m0 = blockIdx.y * 128;
    const int n0 = blockIdx.x * 128;
    const int tid = threadIdx.x;
    const int tx = tid & 15;     // 0..15 -> 8 cols each
    const int ty = tid >> 4;     // 0..15 -> 8 rows each

    float acc[8][8];
#pragma unroll
    for (int i = 0; i < 8; i++)
#pragma unroll
        for (int j = 0; j < 8; j++) acc[i][j] = 0.f;

    for (int k0 = 0; k0 < K; k0 += 8) {
        if (TRANSA) {
            // tile element (m,k) at Araw[(k0+kk)*lda + m0+mm]; m contiguous -> coalesced
            const int kk = tid >> 5, mm = (tid & 31) * 4;
            float4 v = *(const float4*)&A[(long)(k0 + kk) * lda + m0 + mm];
            *(float4*)&As[kk][mm] = v;
        } else {
            const int row = tid >> 1, cg = (tid & 1) * 4;
            float4 v = *(const float4*)&A[(long)(m0 + row) * lda + k0 + cg];
            As[cg + 0][row] = v.x;
            As[cg + 1][row] = v.y;
            As[cg + 2][row] = v.z;
            As[cg + 3][row] = v.w;
        }
        {
            const int kk = tid >> 5, nn = (tid & 31) * 4;
            float4 v = *(const float4*)&B[(long)(k0 + kk) * ldb + n0 + nn];
            *(float4*)&Bs[kk][nn] = v;
        }
        __syncthreads();

#pragma unroll
        for (int kk = 0; kk < 8; kk++) {
            float4 a0 = *(const float4*)&As[kk][ty * 8];
            float4 a1 = *(const float4*)&As[kk][ty * 8 + 4];
            float4 b0 = *(const float4*)&Bs[kk][tx * 8];
            float4 b1 = *(const float4*)&Bs[kk][tx * 8 + 4];
            float av_[8] = {a0.x, a0.y, a0.z, a0.w, a1.x, a1.y, a1.z, a1.w};
            float bv_[8] = {b0.x, b0.y, b0.z, b0.w, b1.x, b1.y, b1.z, b1.w};
#pragma unroll
            for (int i = 0; i < 8; i++)
#pragma unroll
                for (int j = 0; j < 8; j++) acc[i][j] += av_[i] * bv_[j];
        }
        __syncthreads();
    }

    // 8 consecutive output cols stay inside one head block (DOUT=64 % 8 == 0)
    const int hcol = (n0 + tx * 8) / DOUT;
#pragma unroll
    for (int i = 0; i < 8; i++) {
        const int row = m0 + ty * 8 + i;
        float scale = 1.f;
        if (EPI) scale = aeb[row * HEADS + hcol];
        float4 o0, o1;
        o0.x = acc[i][0] * scale; o0.y = acc[i][1] * scale;
        o0.z = acc[i][2] * scale; o0.w = acc[i][3] * scale;
        o1.x = acc[i][4] * scale; o1.y = acc[i][5] * scale;
        o1.z = acc[i][6] * scale; o1.w = acc[i][7] * scale;
        float* cp = &C[(long)row * ldc + n0 + tx * 8];
        *(float4*)cp = o0;
        *(float4*)(cp + 4) = o1;
    }
}

// ---------------- av[b,n,h] = leaky_relu( dot(Wh[b,n,h,:], a) ) ----------------
// one warp per (b,n,h); 2 elements per lane + shfl reduction
__global__ __launch_bounds__(256) void av_kernel(const float* __restrict__ a)
{
    const int item = blockIdx.x * 8 + (threadIdx.x >> 5);   // (b*N + n)*HEADS + h
    const int lane = threadIdx.x & 31;
    const float* wh = g_Wh + (long)item * DOUT;
    float s = wh[lane] * a[lane] + wh[lane + 32] * a[lane + 32];
#pragma unroll
    for (int o = 16; o; o >>= 1) s += __shfl_xor_sync(0xffffffffu, s, o);
    if (lane == 0) g_av[item] = fmaxf(s, 0.f) + LRELU_ALPHA * fminf(s, 0.f);
}

// ---------------- logits partials: part[s][b][e][h] = sum_{n in slice s} H[n,e]*av[b,n,h]
__global__ __launch_bounds__(256) void logits_kernel(const float* __restrict__ H)
{
    const int e = blockIdx.x * 256 + threadIdx.x;   // blockIdx.x in [0,16)
    const int slice = blockIdx.y;                   // [0,16)
    const int nbeg = slice * (N_DIM / NSLICE);      // 512 n's per slice

    float acc[16];
#pragma unroll
    for (int j = 0; j < 16; j++) acc[j] = 0.f;

    __shared__ float avs[64][16];
    for (int nc = 0; nc < N_DIM / NSLICE; nc += 64) {
        __syncthreads();
        for (int i = threadIdx.x; i < 64 * 16; i += 256) {
            const int nn = i >> 4, bh = i & 15;
            const int bb = bh >> 3, hh = bh & 7;
            avs[nn][bh] = g_av[((long)bb * N_DIM + nbeg + nc + nn) * HEADS + hh];
        }
        __syncthreads();
        for (int nn = 0; nn < 64; nn++) {
            const float hv = H[(long)(nbeg + nc + nn) * E_DIM + e];
#pragma unroll
            for (int j = 0; j < 16; j++) acc[j] += hv * avs[nn][j];
        }
    }
#pragma unroll
    for (int j = 0; j < 16; j++) {
        const int bb = j >> 3, hh = j & 7;
        g_part[(((long)slice * BATCH + bb) * E_DIM + e) * HEADS + hh] = acc[j];
    }
}

// ---------------- softmax over E per (b,h); sums the NSLICE partials first ----
__global__ __launch_bounds__(256) void softmax_kernel()
{
    const int bb = blockIdx.x >> 3, hh = blockIdx.x & 7;
    const int t = threadIdx.x;
    float v[E_DIM / 256];
    float mx = -1e30f;
#pragma unroll
    for (int i = 0; i < E_DIM / 256; i++) {
        const int e = i * 256 + t;
        float s = 0.f;
        for (int sl = 0; sl < NSLICE; sl++)
            s += g_part[(((long)sl * BATCH + bb) * E_DIM + e) * HEADS + hh];
        v[i] = s;
        mx = fmaxf(mx, s);
    }
    __shared__ float red[256];
    red[t] = mx; __syncthreads();
    for (int o = 128; o; o >>= 1) { if (t < o) red[t] = fmaxf(red[t], red[t + o]); __syncthreads(); }
    mx = red[0]; __syncthreads();

    float sum = 0.f;
#pragma unroll
    for (int i = 0; i < E_DIM / 256; i++) { v[i] = __expf(v[i] - mx); sum += v[i]; }
    red[t] = sum; __syncthreads();
    for (int o = 128; o; o >>= 1) { if (t < o) red[t] += red[t + o]; __syncthreads(); }
    const float inv = 1.f / red[0];
#pragma unroll
    for (int i = 0; i < E_DIM / 256; i++) {
        const int e = i * 256 + t;
        g_ae[((long)bb * E_DIM + e) * HEADS + hh] = v[i] * inv;
    }
}

// ---------------- launch ----------------
extern "C" void kernel_launch(void* const* d_in, const int* in_sizes, int n_in,
                              void* d_out, int out_size)
{
    const float* x = (const float*)d_in[0];   // (B, N, FIN)
    const float* H = (const float*)d_in[1];   // (N, E)
    const float* W = (const float*)d_in[2];   // (FIN, HD)
    const float* a = (const float*)d_in[3];   // (DOUT, 1)
    float* out = (float*)d_out;               // (B, N, HD)

    float *pWh, *pm2, *pae;
    cudaGetSymbolAddress((void**)&pWh, g_Wh);
    cudaGetSymbolAddress((void**)&pm2, g_m2);
    cudaGetSymbolAddress((void**)&pae, g_ae);

    // 1) Wh = x @ W : (B*N, HD, FIN)
    {
        dim3 grid(HD / 128, (BATCH * N_DIM) / 128, 1);
        sgemm128<false, false><<<grid, 256>>>(x, W, pWh,
            BATCH * N_DIM, HD, FIN, FIN, HD, HD, 0, 0, 0, nullptr, 0);
    }
    // 2) av
    av_kernel<<<BATCH * N_DIM * HEADS / 8, 256>>>(a);
    // 3) logits partials
    logits_kernel<<<dim3(E_DIM / 256, NSLICE), 256>>>(H);
    // 4) softmax -> ae
    softmax_kernel<<<BATCH * HEADS, 256>>>();
    // 5) m2[b] = (H^T @ Wh[b]) scaled by ae in epilogue : (E, HD, N)
    {
        dim3 grid(HD / 128, E_DIM / 128, BATCH);
        sgemm128<true, true><<<grid, 256>>>(H, pWh, pm2,
            E_DIM, HD, N_DIM, E_DIM, HD, HD,
            0, (long)N_DIM * HD, (long)E_DIM * HD, pae, (long)E_DIM * HEADS);
    }
    // 6) out[b] = H @ m2[b] : (N, HD, E)
    {
        dim3 grid(HD / 128, N_DIM / 128, BATCH);
        sgemm128<false, false><<<grid, 256>>>(H, pm2, out,
            N_DIM, HD, E_DIM, E_DIM, HD, HD,
            0, (long)E_DIM * HD, (long)N_DIM * HD, nullptr, 0);
    }
}

// round 2
// speedup vs baseline: 1.0047x; 1.0047x over previous
#include <cuda_runtime.h>
#include <cstdint>

#define E_DIM 4096
#define N_DIM 8192
#define FIN   256
#define HEADS 8
#define DOUT  64
#define HD    512      // HEADS*DOUT
#define BATCH 2
#define LRELU_ALPHA 0.2f
#define NSLICE 16

// ---------------- scratch (allocation-free: __device__ globals) ----------------
__device__ float g_Wh[BATCH * N_DIM * HD];                 // (b,n,h,d)
__device__ float g_av[BATCH * N_DIM * HEADS];              // (b,n,h)
__device__ float g_part[NSLICE * BATCH * E_DIM * HEADS];   // sliced logits partials
__device__ float g_ae[BATCH * E_DIM * HEADS];              // softmaxed edge attention
__device__ float g_m2[BATCH * E_DIM * HD];                 // ae-scaled edge features

__device__ __forceinline__ uint32_t f2tf32(float f) {
    uint32_t r;
    asm("cvt.rna.tf32.f32 %0, %1;" : "=r"(r) : "f"(f));
    return r;
}

#define MMA_TF32(c, a, b) \
    asm volatile("mma.sync.aligned.m16n8k8.row.col.f32.tf32.tf32.f32 " \
        "{%0,%1,%2,%3}, {%4,%5,%6,%7}, {%8,%9}, {%0,%1,%2,%3};" \
        : "+f"((c)[0]), "+f"((c)[1]), "+f"((c)[2]), "+f"((c)[3]) \
        : "r"((a)[0]), "r"((a)[1]), "r"((a)[2]), "r"((a)[3]), \
          "r"((b)[0]), "r"((b)[1]))

// ---------------- tf32 tensor-core GEMM: 128x128x16 tile, 8 warps ----------------
// TRANSA=false: A row-major M x K (lda = row stride)
// TRANSA=true : logical A[m,k] = Araw[k*lda + m]
// EPI=true    : C[m, col] *= ae[m*HEADS + col/DOUT]
template<bool TRANSA, bool EPI>
__global__ __launch_bounds__(256) void tgemm(
    const float* __restrict__ A, const float* __restrict__ B, float* __restrict__ C,
    int K, int lda, int ldb, int ldc,
    long strideA, long strideB, long strideC,
    const float* __restrict__ ae, long strideAe)
{
    // fragment-major smem: A [buf][kk][mtile][lane][slot4], B [buf][kk][ntile][lane][slot2]
    __shared__ uint32_t As[2][2][8][32][4];    // 16 KB
    __shared__ uint32_t Bs[2][2][16][32][2];   // 16 KB

    const int b = blockIdx.z;
    A += (long)b * strideA;
    B += (long)b * strideB;
    C += (long)b * strideC;
    const float* aeb = EPI ? (ae + (long)b * strideAe) : nullptr;

    const int m0 = blockIdx.y * 128;
    const int n0 = blockIdx.x * 128;
    const int tid = threadIdx.x;
    const int lane = tid & 31;
    const int wid = tid >> 5;
    const int wm = wid >> 1;   // 0..3 -> 32 rows
    const int wn = wid & 1;    // 0..1 -> 64 cols (exactly one head)

    float acc[2][8][4];
#pragma unroll
    for (int i = 0; i < 2; i++)
#pragma unroll
        for (int nt = 0; nt < 8; nt++)
#pragma unroll
            for (int s = 0; s < 4; s++) acc[i][nt][s] = 0.f;

    float4 ra[2], rb[2];

    auto ldtile = [&](int k0) {
#pragma unroll
        for (int r = 0; r < 2; r++) {
            const int idx = tid + r * 256;
            if (TRANSA) {
                const int kx = idx >> 5, p = idx & 31;
                ra[r] = *(const float4*)&A[(long)(k0 + kx) * lda + m0 + 4 * p];
            } else {
                const int m = idx >> 2, q = idx & 3;
                ra[r] = *(const float4*)&A[(long)(m0 + m) * lda + k0 + 4 * q];
            }
        }
#pragma unroll
        for (int r = 0; r < 2; r++) {
            const int idx = tid + r * 256;
            const int k = idx >> 5, q = idx & 31;
            rb[r] = *(const float4*)&B[(long)(k0 + k) * ldb + n0 + 4 * q];
        }
    };

    auto sttile = [&](int buf) {
#pragma unroll
        for (int r = 0; r < 2; r++) {
            const int idx = tid + r * 256;
            const float* fp = reinterpret_cast<const float*>(&ra[r]);
            if (TRANSA) {
                const int kx = idx >> 5, p = idx & 31;
#pragma unroll
                for (int j = 0; j < 4; j++) {
                    const int m = 4 * p + j;
                    As[buf][kx >> 3][m >> 4][(m & 7) * 4 + (kx & 3)]
                      [((kx & 7) >= 4) * 2 + ((m & 15) >= 8)] = f2tf32(fp[j]);
                }
            } else {
                const int m = idx >> 2, q = idx & 3;
#pragma unroll
                for (int j = 0; j < 4; j++) {
                    const int k = 4 * q + j;
                    As[buf][k >> 3][m >> 4][(m & 7) * 4 + (k & 3)]
                      [((k & 7) >= 4) * 2 + ((m & 15) >= 8)] = f2tf32(fp[j]);
                }
            }
        }
#pragma unroll
        for (int r = 0; r < 2; r++) {
            const int idx = tid + r * 256;
            const float* fp = reinterpret_cast<const float*>(&rb[r]);
            const int k = idx >> 5, q = idx & 31;
#pragma unroll
            for (int j = 0; j < 4; j++) {
                const int n = 4 * q + j;
                Bs[buf][k >> 3][n >> 3][(n & 7) * 4 + (k & 3)][(k & 7) >= 4] = f2tf32(fp[j]);
            }
        }
    };

    auto compute = [&](int buf) {
#pragma unroll
        for (int kk = 0; kk < 2; kk++) {
            uint32_t af[2][4];
            uint32_t bf[8][2];
#pragma unroll
            for (int i = 0; i < 2; i++)
                *(uint4*)af[i] = *(const uint4*)&As[buf][kk][wm * 2 + i][lane][0];
#pragma unroll
            for (int nt = 0; nt < 8; nt++)
                *(uint2*)bf[nt] = *(const uint2*)&Bs[buf][kk][wn * 8 + nt][lane][0];
#pragma unroll
            for (int i = 0; i < 2; i++)
#pragma unroll
                for (int nt = 0; nt < 8; nt++)
                    MMA_TF32(acc[i][nt], af[i], bf[nt]);
        }
    };

    const int T = K / 16;
    ldtile(0);
    sttile(0);
    int buf = 0;
    for (int t = 0; t < T; t++) {
        __syncthreads();
        if (t + 1 < T) ldtile((t + 1) * 16);
        compute(buf);
        if (t + 1 < T) sttile(buf ^ 1);
        buf ^= 1;
    }

    // epilogue: each warp covers exactly one head's 64 cols
    const int head = (n0 >> 6) + wn;
#pragma unroll
    for (int i = 0; i < 2; i++) {
        const int row0 = m0 + wm * 32 + i * 16 + (lane >> 2);
        float s0 = 1.f, s1 = 1.f;
        if (EPI) {
            s0 = aeb[row0 * HEADS + head];
            s1 = aeb[(row0 + 8) * HEADS + head];
        }
#pragma unroll
        for (int nt = 0; nt < 8; nt++) {
            const int col = n0 + wn * 64 + nt * 8 + 2 * (lane & 3);
            float2 v0 = {acc[i][nt][0] * s0, acc[i][nt][1] * s0};
            float2 v1 = {acc[i][nt][2] * s1, acc[i][nt][3] * s1};
            *(float2*)&C[(long)row0 * ldc + col] = v0;
            *(float2*)&C[(long)(row0 + 8) * ldc + col] = v1;
        }
    }
}

// ---------------- av[b,n,h] = leaky_relu( dot(Wh[b,n,h,:], a) ) ----------------
__global__ __launch_bounds__(256) void av_kernel(const float* __restrict__ a)
{
    const int item = blockIdx.x * 8 + (threadIdx.x >> 5);
    const int lane = threadIdx.x & 31;
    const float* wh = g_Wh + (long)item * DOUT;
    float s = wh[lane] * a[lane] + wh[lane + 32] * a[lane + 32];
#pragma unroll
    for (int o = 16; o; o >>= 1) s += __shfl_xor_sync(0xffffffffu, s, o);
    if (lane == 0) g_av[item] = fmaxf(s, 0.f) + LRELU_ALPHA * fminf(s, 0.f);
}

// ---------------- logits partials ----------------
__global__ __launch_bounds__(256) void logits_kernel(const float* __restrict__ H)
{
    const int e = blockIdx.x * 256 + threadIdx.x;
    const int slice = blockIdx.y;
    const int nbeg = slice * (N_DIM / NSLICE);

    float acc[16];
#pragma unroll
    for (int j = 0; j < 16; j++) acc[j] = 0.f;

    __shared__ float avs[64][16];
    for (int nc = 0; nc < N_DIM / NSLICE; nc += 64) {
        __syncthreads();
        for (int i = threadIdx.x; i < 64 * 16; i += 256) {
            const int nn = i >> 4, bh = i & 15;
            const int bb = bh >> 3, hh = bh & 7;
            avs[nn][bh] = g_av[((long)bb * N_DIM + nbeg + nc + nn) * HEADS + hh];
        }
        __syncthreads();
        for (int nn = 0; nn < 64; nn++) {
            const float hv = H[(long)(nbeg + nc + nn) * E_DIM + e];
#pragma unroll
            for (int j = 0; j < 16; j++) acc[j] += hv * avs[nn][j];
        }
    }
#pragma unroll
    for (int j = 0; j < 16; j++) {
        const int bb = j >> 3, hh = j & 7;
        g_part[(((long)slice * BATCH + bb) * E_DIM + e) * HEADS + hh] = acc[j];
    }
}

// ---------------- softmax over E per (b,h) ----------------
__global__ __launch_bounds__(256) void softmax_kernel()
{
    const int bb = blockIdx.x >> 3, hh = blockIdx.x & 7;
    const int t = threadIdx.x;
    float v[E_DIM / 256];
    float mx = -1e30f;
#pragma unroll
    for (int i = 0; i < E_DIM / 256; i++) {
        const int e = i * 256 + t;
        float s = 0.f;
        for (int sl = 0; sl < NSLICE; sl++)
            s += g_part[(((long)sl * BATCH + bb) * E_DIM + e) * HEADS + hh];
        v[i] = s;
        mx = fmaxf(mx, s);
    }
    __shared__ float red[256];
    red[t] = mx; __syncthreads();
    for (int o = 128; o; o >>= 1) { if (t < o) red[t] = fmaxf(red[t], red[t + o]); __syncthreads(); }
    mx = red[0]; __syncthreads();

    float sum = 0.f;
#pragma unroll
    for (int i = 0; i < E_DIM / 256; i++) { v[i] = __expf(v[i] - mx); sum += v[i]; }
    red[t] = sum; __syncthreads();
    for (int o = 128; o; o >>= 1) { if (t < o) red[t] += red[t + o]; __syncthreads(); }
    const float inv = 1.f / red[0];
#pragma unroll
    for (int i = 0; i < E_DIM / 256; i++) {
        const int e = i * 256 + t;
        g_ae[((long)bb * E_DIM + e) * HEADS + hh] = v[i] * inv;
    }
}

// ---------------- launch ----------------
extern "C" void kernel_launch(void* const* d_in, const int* in_sizes, int n_in,
                              void* d_out, int out_size)
{
    const float* x = (const float*)d_in[0];   // (B, N, FIN)
    const float* H = (const float*)d_in[1];   // (N, E)
    const float* W = (const float*)d_in[2];   // (FIN, HD)
    const float* a = (const float*)d_in[3];   // (DOUT, 1)
    float* out = (float*)d_out;               // (B, N, HD)

    float *pWh, *pm2, *pae;
    cudaGetSymbolAddress((void**)&pWh, g_Wh);
    cudaGetSymbolAddress((void**)&pm2, g_m2);
    cudaGetSymbolAddress((void**)&pae, g_ae);

    // 1) Wh = x @ W : M = B*N = 16384, N = 512, K = 256
    {
        dim3 grid(HD / 128, (BATCH * N_DIM) / 128, 1);
        tgemm<false, false><<<grid, 256>>>(x, W, pWh,
            FIN, FIN, HD, HD, 0, 0, 0, nullptr, 0);
    }
    // 2) av
    av_kernel<<<BATCH * N_DIM * HEADS / 8, 256>>>(a);
    // 3) logits partials
    logits_kernel<<<dim3(E_DIM / 256, NSLICE), 256>>>(H);
    // 4) softmax -> ae
    softmax_kernel<<<BATCH * HEADS, 256>>>();
    // 5) m2[b] = (H^T @ Wh[b]) * ae : M = E = 4096, N = 512, K = N_DIM = 8192
    {
        dim3 grid(HD / 128, E_DIM / 128, BATCH);
        tgemm<true, true><<<grid, 256>>>(H, pWh, pm2,
            N_DIM, E_DIM, HD, HD,
            0, (long)N_DIM * HD, (long)E_DIM * HD, pae, (long)E_DIM * HEADS);
    }
    // 6) out[b] = H @ m2[b] : M = N_DIM = 8192, N = 512, K = E = 4096
    {
        dim3 grid(HD / 128, N_DIM / 128, BATCH);
        tgemm<false, false><<<grid, 256>>>(H, pm2, out,
            E_DIM, E_DIM, HD, HD,
            0, (long)E_DIM * HD, (long)N_DIM * HD, nullptr, 0);
    }
}

// round 4
// speedup vs baseline: 3.0240x; 3.0099x over previous
#include <cuda_runtime.h>
#include <cstdint>

#define E_DIM 4096
#define N_DIM 8192
#define FIN   256
#define HEADS 8
#define DOUT  64
#define HD    512
#define BATCH 2
#define LRELU_ALPHA 0.2f
#define NSLICE 16

// ---------------- scratch (16B aligned for cp.async) ----------------
__device__ __align__(16) float g_xr[BATCH * N_DIM * FIN];
__device__ __align__(16) float g_Wr[FIN * HD];
__device__ __align__(16) float g_Hr[N_DIM * E_DIM];
__device__ __align__(16) float g_HT[E_DIM * N_DIM];
__device__ __align__(16) float g_Wh[BATCH * N_DIM * HD];
__device__ __align__(16) float g_m2[BATCH * E_DIM * HD];
__device__ float g_av[BATCH * N_DIM * HEADS];
__device__ float g_part[NSLICE * BATCH * E_DIM * HEADS];
__device__ float g_ae[BATCH * E_DIM * HEADS];

__device__ __forceinline__ uint32_t f2tf32(float f) {
    uint32_t r; asm("cvt.rna.tf32.f32 %0, %1;" : "=r"(r) : "f"(f)); return r;
}
__device__ __forceinline__ uint32_t smem_u32(const void* p) {
    uint32_t a;
    asm("{ .reg .u64 t; cvta.to.shared.u64 t, %1; cvt.u32.u64 %0, t; }" : "=r"(a) : "l"(p));
    return a;
}
__device__ __forceinline__ uint32_t lds32(uint32_t a) {
    uint32_t v; asm volatile("ld.shared.b32 %0, [%1];" : "=r"(v) : "r"(a)); return v;
}
__device__ __forceinline__ void cpa16(uint32_t dst, const void* src) {
    asm volatile("cp.async.cg.shared.global [%0], [%1], 16;" :: "r"(dst), "l"(src));
}

#define MMA_TF32(c, a, b) \
    asm volatile("mma.sync.aligned.m16n8k8.row.col.f32.tf32.tf32.f32 " \
        "{%0,%1,%2,%3}, {%4,%5,%6,%7}, {%8,%9}, {%0,%1,%2,%3};" \
        : "+f"((c)[0]), "+f"((c)[1]), "+f"((c)[2]), "+f"((c)[3]) \
        : "r"((a)[0]), "r"((a)[1]), "r"((a)[2]), "r"((a)[3]), \
          "r"((b)[0]), "r"((b)[1]))

#define STAGES 4
#define STG_BYTES 16384               // A 8KB + B 8KB per stage
#define SMEM_SZ (STAGES * STG_BYTES)  // 64 KB

// ---------------- pipelined tf32 mma GEMM: 128x128 CTA tile, K-step 16 ----------------
// A: M x K row-major natural (lda). B: K x N row-major natural (ldb), N cols = HD.
// EPI 0: round output (tf32)   EPI 1: scale by ae[(bz,row,head)] then round   EPI 2: plain
template<int EPI>
__global__ void __launch_bounds__(256, 2) tgemm(
    const float* __restrict__ A, const float* __restrict__ B, float* __restrict__ C,
    int K, int lda, int ldb, long strideB, long strideC, const float* __restrict__ ae)
{
    extern __shared__ char smem[];
    const uint32_t sb = smem_u32(smem);
    const int tid = threadIdx.x, lane = tid & 31, wid = tid >> 5;
    const int wm = wid >> 1, wn = wid & 1;
    const int m0 = blockIdx.y * 128, n0 = blockIdx.x * 128, bz = blockIdx.z;

    const float* Ag = A + (long)m0 * lda;
    const float* Bg = B + (long)bz * strideB + n0;

    // per-thread loader coords (2 chunks of A, 2 of B per stage)
    // A: 128 rows x 4 groups of 16B ; swizzled group g^((row>>1)&3)
    // B: 16 rows x 32 groups of 16B ; swizzled group g^((2k)&31)
    auto load_stage = [&](int st, int k0) {
        const uint32_t sA = sb + st * STG_BYTES;
        const uint32_t sBs = sA + 8192;
#pragma unroll
        for (int j = 0; j < 2; j++) {
            const int id = tid + j * 256;
            const int row = id >> 2, g = id & 3;
            cpa16(sA + row * 64 + ((g ^ ((row >> 1) & 3)) << 4),
                  Ag + (long)row * lda + k0 + g * 4);
        }
#pragma unroll
        for (int j = 0; j < 2; j++) {
            const int id = tid + j * 256;
            const int k = id >> 5, g = id & 31;
            cpa16(sBs + k * 512 + ((g ^ ((2 * k) & 31)) << 4),
                  Bg + (long)(k0 + k) * ldb + g * 4);
        }
    };

    float acc[2][8][4];
#pragma unroll
    for (int mt = 0; mt < 2; mt++)
#pragma unroll
        for (int nt = 0; nt < 8; nt++)
#pragma unroll
            for (int s = 0; s < 4; s++) acc[mt][nt][s] = 0.f;

    // fragment-load invariants
    const int mA = wm * 32 + (lane >> 2);     // a0 row for mt=0
    const int sw = (mA >> 1) & 3;             // same for rows +8/+16/+24
    const int cl = lane & 3;
    const int rn = (lane >> 2) & 3;           // n & 3
    const int qb = wn * 16 + ((lane >> 2) >> 2); // (n>>2) base before nt*2
    uint32_t rowA[2][2];
#pragma unroll
    for (int mt = 0; mt < 2; mt++) {
        rowA[mt][0] = (mA + mt * 16) * 64;
        rowA[mt][1] = (mA + mt * 16 + 8) * 64;
    }

    const int T = K / 16;
    // prologue: 3 stages
    for (int t = 0; t < 3; t++) {
        load_stage(t, t * 16);
        asm volatile("cp.async.commit_group;" ::: "memory");
    }

    for (int t = 0; t < T; t++) {
        asm volatile("cp.async.wait_group 2;" ::: "memory");
        __syncthreads();
        const int u = t + 3;
        if (u < T) load_stage(u & 3, u * 16);
        asm volatile("cp.async.commit_group;" ::: "memory");  // always commit (empty ok)

        const uint32_t Ab = sb + (t & 3) * STG_BYTES;
        const uint32_t Bb = Ab + 8192;
#pragma unroll
        for (int kk = 0; kk < 2; kk++) {
            uint32_t af[2][4], bf[8][2];
            const int co0 = (((kk * 2) ^ sw) << 4) + cl * 4;
            const int co1 = (((kk * 2 + 1) ^ sw) << 4) + cl * 4;
#pragma unroll
            for (int mt = 0; mt < 2; mt++) {
                af[mt][0] = lds32(Ab + rowA[mt][0] + co0);
                af[mt][1] = lds32(Ab + rowA[mt][1] + co0);
                af[mt][2] = lds32(Ab + rowA[mt][0] + co1);
                af[mt][3] = lds32(Ab + rowA[mt][1] + co1);
            }
#pragma unroll
            for (int h = 0; h < 2; h++) {
                const int k = kk * 8 + h * 4 + cl;
                const uint32_t base = Bb + k * 512 + rn * 4;
                const int x2 = (2 * k) & 31;
#pragma unroll
                for (int nt = 0; nt < 8; nt++)
                    bf[nt][h] = lds32(base + ((((qb + nt * 2) ^ x2) & 31) << 4));
            }
#pragma unroll
            for (int mt = 0; mt < 2; mt++)
#pragma unroll
                for (int nt = 0; nt < 8; nt++)
                    MMA_TF32(acc[mt][nt], af[mt], bf[nt]);
        }
    }

    // epilogue: warp covers rows [m0+wm*32, +32) x cols [n0+wn*64, +64) (= one head)
    float* Cb = C + (long)bz * strideC;
    const int head = (n0 >> 6) + wn;
#pragma unroll
    for (int mt = 0; mt < 2; mt++) {
        const int row0 = m0 + wm * 32 + mt * 16 + (lane >> 2);
        float s0 = 1.f, s1 = 1.f;
        if (EPI == 1) {
            s0 = ae[((long)bz * E_DIM + row0) * HEADS + head];
            s1 = ae[((long)bz * E_DIM + row0 + 8) * HEADS + head];
        }
#pragma unroll
        for (int nt = 0; nt < 8; nt++) {
            const int col = n0 + wn * 64 + nt * 8 + 2 * (lane & 3);
            float v0 = acc[mt][nt][0] * s0, v1 = acc[mt][nt][1] * s0;
            float v2 = acc[mt][nt][2] * s1, v3 = acc[mt][nt][3] * s1;
            if (EPI != 2) {
                v0 = __uint_as_float(f2tf32(v0)); v1 = __uint_as_float(f2tf32(v1));
                v2 = __uint_as_float(f2tf32(v2)); v3 = __uint_as_float(f2tf32(v3));
            }
            float2 o0 = {v0, v1}, o1 = {v2, v3};
            *(float2*)&Cb[(long)row0 * HD + col] = o0;
            *(float2*)&Cb[(long)(row0 + 8) * HD + col] = o1;
        }
    }
}

// ---------------- prep kernels ----------------
__global__ __launch_bounds__(256) void prep_round(const float* __restrict__ src,
                                                  float* __restrict__ dst) {
    const int i = blockIdx.x * 256 + threadIdx.x;
    float4 v = ((const float4*)src)[i];
    uint4 o = {f2tf32(v.x), f2tf32(v.y), f2tf32(v.z), f2tf32(v.w)};
    ((uint4*)dst)[i] = o;
}
__global__ __launch_bounds__(256) void prep_H(const float* __restrict__ H) {
    __shared__ float ts[32][33];
    const int e0 = blockIdx.x * 32, n0 = blockIdx.y * 32;
    const int tx = threadIdx.x & 31, ty = threadIdx.x >> 5;
#pragma unroll
    for (int r8 = 0; r8 < 4; r8++) {
        const int nl = ty + r8 * 8;
        const float v = __uint_as_float(f2tf32(H[(long)(n0 + nl) * E_DIM + e0 + tx]));
        g_Hr[(long)(n0 + nl) * E_DIM + e0 + tx] = v;
        ts[tx][nl] = v;
    }
    __syncthreads();
#pragma unroll
    for (int r8 = 0; r8 < 4; r8++) {
        const int el = ty + r8 * 8;
        g_HT[(long)(e0 + el) * N_DIM + n0 + tx] = ts[el][tx];
    }
}

// ---------------- av / logits / softmax ----------------
__global__ __launch_bounds__(256) void av_kernel(const float* __restrict__ a) {
    const int item = blockIdx.x * 8 + (threadIdx.x >> 5);
    const int lane = threadIdx.x & 31;
    const float* wh = g_Wh + (long)item * DOUT;
    float s = wh[lane] * a[lane] + wh[lane + 32] * a[lane + 32];
#pragma unroll
    for (int o = 16; o; o >>= 1) s += __shfl_xor_sync(0xffffffffu, s, o);
    if (lane == 0) g_av[item] = fmaxf(s, 0.f) + LRELU_ALPHA * fminf(s, 0.f);
}

__global__ __launch_bounds__(256) void logits_kernel(const float* __restrict__ H) {
    const int e = blockIdx.x * 256 + threadIdx.x;
    const int slice = blockIdx.y;
    const int nbeg = slice * (N_DIM / NSLICE);
    float acc[16];
#pragma unroll
    for (int j = 0; j < 16; j++) acc[j] = 0.f;
    __shared__ float avs[64][16];
    for (int nc = 0; nc < N_DIM / NSLICE; nc += 64) {
        __syncthreads();
        for (int i = threadIdx.x; i < 64 * 16; i += 256) {
            const int nn = i >> 4, bh = i & 15;
            avs[nn][bh] = g_av[((long)(bh >> 3) * N_DIM + nbeg + nc + nn) * HEADS + (bh & 7)];
        }
        __syncthreads();
        for (int nn = 0; nn < 64; nn++) {
            const float hv = H[(long)(nbeg + nc + nn) * E_DIM + e];
#pragma unroll
            for (int j = 0; j < 16; j++) acc[j] += hv * avs[nn][j];
        }
    }
#pragma unroll
    for (int j = 0; j < 16; j++)
        g_part[(((long)slice * BATCH + (j >> 3)) * E_DIM + e) * HEADS + (j & 7)] = acc[j];
}

__global__ __launch_bounds__(256) void softmax_kernel() {
    const int bb = blockIdx.x >> 3, hh = blockIdx.x & 7;
    const int t = threadIdx.x;
    float v[E_DIM / 256];
    float mx = -1e30f;
#pragma unroll
    for (int i = 0; i < E_DIM / 256; i++) {
        const int e = i * 256 + t;
        float s = 0.f;
        for (int sl = 0; sl < NSLICE; sl++)
            s += g_part[(((long)sl * BATCH + bb) * E_DIM + e) * HEADS + hh];
        v[i] = s; mx = fmaxf(mx, s);
    }
    __shared__ float red[256];
    red[t] = mx; __syncthreads();
    for (int o = 128; o; o >>= 1) { if (t < o) red[t] = fmaxf(red[t], red[t + o]); __syncthreads(); }
    mx = red[0]; __syncthreads();
    float sum = 0.f;
#pragma unroll
    for (int i = 0; i < E_DIM / 256; i++) { v[i] = __expf(v[i] - mx); sum += v[i]; }
    red[t] = sum; __syncthreads();
    for (int o = 128; o; o >>= 1) { if (t < o) red[t] += red[t + o]; __syncthreads(); }
    const float inv = 1.f / red[0];
#pragma unroll
    for (int i = 0; i < E_DIM / 256; i++)
        g_ae[((long)bb * E_DIM + i * 256 + t) * HEADS + hh] = v[i] * inv;
}

// ---------------- launch ----------------
extern "C" void kernel_launch(void* const* d_in, const int* in_sizes, int n_in,
                              void* d_out, int out_size)
{
    const float* x = (const float*)d_in[0];
    const float* H = (const float*)d_in[1];
    const float* W = (const float*)d_in[2];
    const float* a = (const float*)d_in[3];
    float* out = (float*)d_out;

    float *pxr, *pWr, *pHr, *pHT, *pWh, *pm2, *pae;
    cudaGetSymbolAddress((void**)&pxr, g_xr);
    cudaGetSymbolAddress((void**)&pWr, g_Wr);
    cudaGetSymbolAddress((void**)&pHr, g_Hr);
    cudaGetSymbolAddress((void**)&pHT, g_HT);
    cudaGetSymbolAddress((void**)&pWh, g_Wh);
    cudaGetSymbolAddress((void**)&pm2, g_m2);
    cudaGetSymbolAddress((void**)&pae, g_ae);

    cudaFuncSetAttribute(tgemm<0>, cudaFuncAttributeMaxDynamicSharedMemorySize, SMEM_SZ);
    cudaFuncSetAttribute(tgemm<1>, cudaFuncAttributeMaxDynamicSharedMemorySize, SMEM_SZ);
    cudaFuncSetAttribute(tgemm<2>, cudaFuncAttributeMaxDynamicSharedMemorySize, SMEM_SZ);

    // prep: tf32-round x, W, H (+ build H^T)
    prep_round<<<BATCH * N_DIM * FIN / 4 / 256, 256>>>(x, pxr);
    prep_round<<<FIN * HD / 4 / 256, 256>>>(W, pWr);
    prep_H<<<dim3(E_DIM / 32, N_DIM / 32), 256>>>(H);

    // 1) Wh = x @ W : M=16384 (flat), K=256  -> rounded
    tgemm<0><<<dim3(HD / 128, (BATCH * N_DIM) / 128, 1), 256, SMEM_SZ>>>(
        pxr, pWr, pWh, FIN, FIN, HD, 0, 0, nullptr);
    // 2) av
    av_kernel<<<BATCH * N_DIM * HEADS / 8, 256>>>(a);
    // 3) logits + softmax (exact fp32 on raw H)
    logits_kernel<<<dim3(E_DIM / 256, NSLICE), 256>>>(H);
    softmax_kernel<<<BATCH * HEADS, 256>>>();
    // 5) m2 = ae * (H^T @ Wh) : M=E, K=N_DIM  -> rounded
    tgemm<1><<<dim3(HD / 128, E_DIM / 128, BATCH), 256, SMEM_SZ>>>(
        pHT, pWh, pm2, N_DIM, N_DIM, HD, (long)N_DIM * HD, (long)E_DIM * HD, pae);
    // 6) out = H @ m2 : M=N_DIM, K=E
    tgemm<2><<<dim3(HD / 128, N_DIM / 128, BATCH), 256, SMEM_SZ>>>(
        pHr, pm2, out, E_DIM, E_DIM, HD, (long)E_DIM * HD, (long)N_DIM * HD, nullptr);
}

// round 5
// speedup vs baseline: 3.8018x; 1.2572x over previous
#include <cuda_runtime.h>
#include <cstdint>

#define E_DIM 4096
#define N_DIM 8192
#define FIN   256
#define HEADS 8
#define DOUT  64
#define HD    512
#define BATCH 2
#define LRELU_ALPHA 0.2f
#define NSLICE 16

// ---------------- scratch ----------------
__device__ __align__(16) float g_xr[BATCH * N_DIM * FIN];    // k-perm cols
__device__ __align__(16) float g_WrT[HD * FIN];              // (hd, fin) k-perm
__device__ __align__(16) float g_Hr[N_DIM * E_DIM];          // e-perm cols
__device__ __align__(16) float g_HT[E_DIM * N_DIM];          // n-perm cols
__device__ __align__(16) float g_Wh[BATCH * N_DIM * HD];     // natural (rounded)
__device__ __align__(16) float g_WhT[BATCH * HD * N_DIM];    // n-perm cols
__device__ __align__(16) float g_m2T[BATCH * HD * E_DIM];    // e-perm cols (rounded, ae-scaled)
__device__ float g_av[BATCH * N_DIM * HEADS];
__device__ float g_part[NSLICE * BATCH * E_DIM * HEADS];
__device__ float g_aeT[BATCH * HEADS * E_DIM];

__device__ __forceinline__ uint32_t f2tf32(float f) {
    uint32_t r; asm("cvt.rna.tf32.f32 %0, %1;" : "=r"(r) : "f"(f)); return r;
}
__device__ __forceinline__ float rnd(float f) { return __uint_as_float(f2tf32(f)); }
__device__ __forceinline__ uint32_t smem_u32(const void* p) {
    uint32_t a;
    asm("{ .reg .u64 t; cvta.to.shared.u64 t, %1; cvt.u32.u64 %0, t; }" : "=r"(a) : "l"(p));
    return a;
}
__device__ __forceinline__ void lds64(uint32_t a, uint32_t& x, uint32_t& y) {
    asm volatile("ld.shared.v2.b32 {%0,%1}, [%2];" : "=r"(x), "=r"(y) : "r"(a));
}
__device__ __forceinline__ void cpa16(uint32_t dst, const void* src) {
    asm volatile("cp.async.cg.shared.global [%0], [%1], 16;" :: "r"(dst), "l"(src));
}
__device__ __host__ __forceinline__ int perm8(int k) { return ((k & 3) << 1) | ((k >> 2) & 1); }
__device__ __forceinline__ int permc(int c) { return (c & ~7) | perm8(c & 7); }

#define MMA_TF32(c, a, b) \
    asm volatile("mma.sync.aligned.m16n8k8.row.col.f32.tf32.tf32.f32 " \
        "{%0,%1,%2,%3}, {%4,%5,%6,%7}, {%8,%9}, {%0,%1,%2,%3};" \
        : "+f"((c)[0]), "+f"((c)[1]), "+f"((c)[2]), "+f"((c)[3]) \
        : "r"((a)[0]), "r"((a)[1]), "r"((a)[2]), "r"((a)[3]), \
          "r"((b)[0]), "r"((b)[1]))

#define STG_BYTES 32768               // A 16KB + B 16KB (128 rows x 128B each)
#define STAGES 3
#define SMEM_SZ (STAGES * STG_BYTES)  // 96 KB

// ---------------- tf32 mma GEMM: CTA 128x128, 4 warps (64x64 each), K-step 32 ----------------
// A: (M x K) rows m, k-perm cols.  B: (N x K) rows n, k-perm cols.  C: (M x N) row-major.
// EPI 0: round   EPI 1: scale by aeT[bz,head(row),e(col)] + round + perm-col store   EPI 2: plain
template<int EPI>
__global__ void __launch_bounds__(128, 2) tgemm(
    const float* __restrict__ A, const float* __restrict__ B, float* __restrict__ C,
    int K, int lda, int ldb, int ldc,
    long strideA, long strideB, long strideC, const float* __restrict__ aeT)
{
    extern __shared__ char smem[];
    const uint32_t sb = smem_u32(smem);
    const int tid = threadIdx.x, lane = tid & 31, wid = tid >> 5;
    const int wm = wid >> 1, wn = wid & 1;
    const int m0 = blockIdx.y * 128, n0 = blockIdx.x * 128, bz = blockIdx.z;

    const float* Ag = A + (long)bz * strideA + (long)m0 * lda;
    const float* Bg = B + (long)bz * strideB + (long)n0 * ldb;

    auto load_stage = [&](int st, int k0) {
        const uint32_t sA = sb + st * STG_BYTES;
#pragma unroll
        for (int i = 0; i < 8; i++) {
            const int id = tid + i * 128;
            const int r = id >> 3, j = id & 7;
            cpa16(sA + r * 128 + ((j ^ ((r & 3) << 1)) << 4), Ag + (long)r * lda + k0 + j * 4);
        }
        const uint32_t sB = sA + 16384;
#pragma unroll
        for (int i = 0; i < 8; i++) {
            const int id = tid + i * 128;
            const int r = id >> 3, j = id & 7;
            cpa16(sB + r * 128 + ((j ^ ((r & 3) << 1)) << 4), Bg + (long)r * ldb + k0 + j * 4);
        }
    };

    float acc[4][8][4];
#pragma unroll
    for (int mt = 0; mt < 4; mt++)
#pragma unroll
        for (int nt = 0; nt < 8; nt++)
#pragma unroll
            for (int s = 0; s < 4; s++) acc[mt][nt][s] = 0.f;

    const int r4 = lane >> 2;                 // 0..7
    const int cl = lane & 3;
    const int swz = (r4 & 3) << 1;
    const int c2 = cl >> 1;
    const int hof = (cl & 1) * 8;

    const int T = K / 32;
    load_stage(0, 0);
    asm volatile("cp.async.commit_group;" ::: "memory");
    load_stage(1, 32);
    asm volatile("cp.async.commit_group;" ::: "memory");

    for (int t = 0; t < T; t++) {
        asm volatile("cp.async.wait_group 1;" ::: "memory");
        __syncthreads();
        const int u = t + 2;
        if (u < T) load_stage(u % 3, u * 32);
        asm volatile("cp.async.commit_group;" ::: "memory");

        const uint32_t Ab = sb + (t % 3) * STG_BYTES;
        const uint32_t Bb = Ab + 16384;
        const uint32_t aBase = Ab + (wm * 64 + r4) * 128 + hof;
        const uint32_t bBase = Bb + (wn * 64 + r4) * 128 + hof;
#pragma unroll
        for (int kk = 0; kk < 4; kk++) {
            const uint32_t gsb = (uint32_t)(((kk * 2 + c2) ^ swz) << 4);
            uint32_t af[4][4], bf[8][2];
#pragma unroll
            for (int mt = 0; mt < 4; mt++) {
                lds64(aBase + mt * 16 * 128 + gsb, af[mt][0], af[mt][2]);
                lds64(aBase + (mt * 16 + 8) * 128 + gsb, af[mt][1], af[mt][3]);
            }
#pragma unroll
            for (int nt = 0; nt < 8; nt++)
                lds64(bBase + nt * 8 * 128 + gsb, bf[nt][0], bf[nt][1]);
#pragma unroll
            for (int mt = 0; mt < 4; mt++)
#pragma unroll
                for (int nt = 0; nt < 8; nt++)
                    MMA_TF32(acc[mt][nt], af[mt], bf[nt]);
        }
    }

    // ---------------- epilogue ----------------
    float* Cb = C + (long)bz * strideC;
    if (EPI == 1) {
        const int head = (m0 >> 6) + wm;
        const float* aeb = aeT + ((long)bz * HEADS + head) * E_DIM;
        float sc0[8], sc1[8]; int cp0[8], cp1[8];
#pragma unroll
        for (int nt = 0; nt < 8; nt++) {
            const int e = n0 + wn * 64 + nt * 8 + 2 * cl;
            sc0[nt] = aeb[e]; sc1[nt] = aeb[e + 1];
            cp0[nt] = (e & ~7) | perm8(e & 7);
            cp1[nt] = (e & ~7) | perm8((e & 7) + 1);
        }
#pragma unroll
        for (int mt = 0; mt < 4; mt++) {
            const int row = m0 + wm * 64 + mt * 16 + r4;
#pragma unroll
            for (int nt = 0; nt < 8; nt++) {
                Cb[(long)row * ldc + cp0[nt]] = rnd(acc[mt][nt][0] * sc0[nt]);
                Cb[(long)row * ldc + cp1[nt]] = rnd(acc[mt][nt][1] * sc1[nt]);
                Cb[(long)(row + 8) * ldc + cp0[nt]] = rnd(acc[mt][nt][2] * sc0[nt]);
                Cb[(long)(row + 8) * ldc + cp1[nt]] = rnd(acc[mt][nt][3] * sc1[nt]);
            }
        }
    } else {
#pragma unroll
        for (int mt = 0; mt < 4; mt++) {
            const int row = m0 + wm * 64 + mt * 16 + r4;
#pragma unroll
            for (int nt = 0; nt < 8; nt++) {
                const int col = n0 + wn * 64 + nt * 8 + 2 * cl;
                float v0 = acc[mt][nt][0], v1 = acc[mt][nt][1];
                float v2 = acc[mt][nt][2], v3 = acc[mt][nt][3];
                if (EPI == 0) { v0 = rnd(v0); v1 = rnd(v1); v2 = rnd(v2); v3 = rnd(v3); }
                float2 o0 = {v0, v1}, o1 = {v2, v3};
                *(float2*)&Cb[(long)row * ldc + col] = o0;
                *(float2*)&Cb[(long)(row + 8) * ldc + col] = o1;
            }
        }
    }
}

// ---------------- prep / transpose kernels ----------------
__global__ __launch_bounds__(256) void prep_x(const float* __restrict__ x) {
    const int i = blockIdx.x * 256 + threadIdx.x;     // float4 id
    const int row = i >> 6, colg = (i & 63) * 4;
    float4 v = ((const float4*)x)[i];
    const float* f = (const float*)&v;
#pragma unroll
    for (int j = 0; j < 4; j++)
        g_xr[(long)row * FIN + (((colg + j) & ~7) | perm8((colg + j) & 7))] = rnd(f[j]);
}
// W (FIN x HD) -> WrT (HD x FIN, k-perm)
__global__ __launch_bounds__(256) void prep_WT(const float* __restrict__ W) {
    __shared__ float ts[32][33];
    const int o0 = blockIdx.x * 32, i0 = blockIdx.y * 32;
    const int tx = threadIdx.x & 31, ty = threadIdx.x >> 5;
#pragma unroll
    for (int r8 = 0; r8 < 4; r8++) {
        const int il = ty + r8 * 8;
        ts[tx][il] = rnd(W[(long)(i0 + il) * HD + o0 + tx]);
    }
    __syncthreads();
#pragma unroll
    for (int r8 = 0; r8 < 4; r8++) {
        const int ol = ty + r8 * 8;
        g_WrT[(long)(o0 + ol) * FIN + i0 + ((tx & ~7) | perm8(tx & 7))] = ts[ol][tx];
    }
}
// H -> Hr (e-perm) and HT (n-perm)
__global__ __launch_bounds__(256) void prep_H(const float* __restrict__ H) {
    __shared__ float ts[32][33];
    const int e0 = blockIdx.x * 32, n0 = blockIdx.y * 32;
    const int tx = threadIdx.x & 31, ty = threadIdx.x >> 5;
    const int txp = (tx & ~7) | perm8(tx & 7);
#pragma unroll
    for (int r8 = 0; r8 < 4; r8++) {
        const int nl = ty + r8 * 8;
        const float v = rnd(H[(long)(n0 + nl) * E_DIM + e0 + tx]);
        g_Hr[(long)(n0 + nl) * E_DIM + e0 + txp] = v;
        ts[tx][nl] = v;
    }
    __syncthreads();
#pragma unroll
    for (int r8 = 0; r8 < 4; r8++) {
        const int el = ty + r8 * 8;
        g_HT[(long)(e0 + el) * N_DIM + n0 + txp] = ts[el][tx];
    }
}
// Wh (B*N x HD) -> WhT (B, HD, N n-perm)
__global__ __launch_bounds__(256) void trWh() {
    __shared__ float ts[32][33];
    const int h0 = blockIdx.x * 32;
    const int n0g = blockIdx.y * 32;                  // global flat n (B*N)
    const int b = n0g >> 13, nn0 = n0g & (N_DIM - 1);
    const int tx = threadIdx.x & 31, ty = threadIdx.x >> 5;
    const int txp = (tx & ~7) | perm8(tx & 7);
#pragma unroll
    for (int r8 = 0; r8 < 4; r8++) {
        const int nl = ty + r8 * 8;
        ts[tx][nl] = g_Wh[(long)(n0g + nl) * HD + h0 + tx];   // ts[hd_l][n_l]
    }
    __syncthreads();
#pragma unroll
    for (int r8 = 0; r8 < 4; r8++) {
        const int hl = ty + r8 * 8;
        g_WhT[((long)b * HD + h0 + hl) * N_DIM + nn0 + txp] = ts[hl][tx];
    }
}

// ---------------- av / logits / softmax ----------------
__global__ __launch_bounds__(256) void av_kernel(const float* __restrict__ a) {
    const int item = blockIdx.x * 8 + (threadIdx.x >> 5);
    const int lane = threadIdx.x & 31;
    const float* wh = g_Wh + (long)item * DOUT;
    float s = wh[lane] * a[lane] + wh[lane + 32] * a[lane + 32];
#pragma unroll
    for (int o = 16; o; o >>= 1) s += __shfl_xor_sync(0xffffffffu, s, o);
    if (lane == 0) g_av[item] = fmaxf(s, 0.f) + LRELU_ALPHA * fminf(s, 0.f);
}

__global__ __launch_bounds__(256) void logits_kernel(const float* __restrict__ H) {
    const int e = blockIdx.x * 256 + threadIdx.x;
    const int slice = blockIdx.y;
    const int nbeg = slice * (N_DIM / NSLICE);
    float acc[16];
#pragma unroll
    for (int j = 0; j < 16; j++) acc[j] = 0.f;
    __shared__ float avs[64][16];
    for (int nc = 0; nc < N_DIM / NSLICE; nc += 64) {
        __syncthreads();
        for (int i = threadIdx.x; i < 64 * 16; i += 256) {
            const int nn = i >> 4, bh = i & 15;
            avs[nn][bh] = g_av[((long)(bh >> 3) * N_DIM + nbeg + nc + nn) * HEADS + (bh & 7)];
        }
        __syncthreads();
        for (int nn = 0; nn < 64; nn++) {
            const float hv = H[(long)(nbeg + nc + nn) * E_DIM + e];
#pragma unroll
            for (int j = 0; j < 16; j++) acc[j] += hv * avs[nn][j];
        }
    }
#pragma unroll
    for (int j = 0; j < 16; j++)
        g_part[(((long)slice * BATCH + (j >> 3)) * E_DIM + e) * HEADS + (j & 7)] = acc[j];
}

__global__ __launch_bounds__(256) void softmax_kernel() {
    const int bb = blockIdx.x >> 3, hh = blockIdx.x & 7;
    const int t = threadIdx.x;
    float v[E_DIM / 256];
    float mx = -1e30f;
#pragma unroll
    for (int i = 0; i < E_DIM / 256; i++) {
        const int e = i * 256 + t;
        float s = 0.f;
        for (int sl = 0; sl < NSLICE; sl++)
            s += g_part[(((long)sl * BATCH + bb) * E_DIM + e) * HEADS + hh];
        v[i] = s; mx = fmaxf(mx, s);
    }
    __shared__ float red[256];
    red[t] = mx; __syncthreads();
    for (int o = 128; o; o >>= 1) { if (t < o) red[t] = fmaxf(red[t], red[t + o]); __syncthreads(); }
    mx = red[0]; __syncthreads();
    float sum = 0.f;
#pragma unroll
    for (int i = 0; i < E_DIM / 256; i++) { v[i] = __expf(v[i] - mx); sum += v[i]; }
    red[t] = sum; __syncthreads();
    for (int o = 128; o; o >>= 1) { if (t < o) red[t] += red[t + o]; __syncthreads(); }
    const float inv = 1.f / red[0];
#pragma unroll
    for (int i = 0; i < E_DIM / 256; i++)
        g_aeT[((long)bb * HEADS + hh) * E_DIM + i * 256 + t] = v[i] * inv;
}

// ---------------- launch ----------------
extern "C" void kernel_launch(void* const* d_in, const int* in_sizes, int n_in,
                              void* d_out, int out_size)
{
    const float* x = (const float*)d_in[0];
    const float* H = (const float*)d_in[1];
    const float* W = (const float*)d_in[2];
    const float* a = (const float*)d_in[3];
    float* out = (float*)d_out;

    float *pxr, *pWrT, *pHr, *pHT, *pWh, *pWhT, *pm2T, *paeT;
    cudaGetSymbolAddress((void**)&pxr, g_xr);
    cudaGetSymbolAddress((void**)&pWrT, g_WrT);
    cudaGetSymbolAddress((void**)&pHr, g_Hr);
    cudaGetSymbolAddress((void**)&pHT, g_HT);
    cudaGetSymbolAddress((void**)&pWh, g_Wh);
    cudaGetSymbolAddress((void**)&pWhT, g_WhT);
    cudaGetSymbolAddress((void**)&pm2T, g_m2T);
    cudaGetSymbolAddress((void**)&paeT, g_aeT);

    cudaFuncSetAttribute(tgemm<0>, cudaFuncAttributeMaxDynamicSharedMemorySize, SMEM_SZ);
    cudaFuncSetAttribute(tgemm<1>, cudaFuncAttributeMaxDynamicSharedMemorySize, SMEM_SZ);
    cudaFuncSetAttribute(tgemm<2>, cudaFuncAttributeMaxDynamicSharedMemorySize, SMEM_SZ);

    prep_x<<<BATCH * N_DIM * FIN / 4 / 256, 256>>>(x);
    prep_WT<<<dim3(HD / 32, FIN / 32), 256>>>(W);
    prep_H<<<dim3(E_DIM / 32, N_DIM / 32), 256>>>(H);

    // 1) Wh = x @ W : A=xr (16384 x 256), B=WrT (512 x 256) -> Wh natural rounded
    tgemm<0><<<dim3(HD / 128, (BATCH * N_DIM) / 128, 1), 128, SMEM_SZ>>>(
        pxr, pWrT, pWh, FIN, FIN, FIN, HD, 0, 0, 0, nullptr);
    // 2) av + 3) logits + 4) softmax (exact fp32)
    av_kernel<<<BATCH * N_DIM * HEADS / 8, 256>>>(a);
    logits_kernel<<<dim3(E_DIM / 256, NSLICE), 256>>>(H);
    softmax_kernel<<<BATCH * HEADS, 256>>>();
    // transpose Wh -> WhT (n-perm)
    trWh<<<dim3(HD / 32, BATCH * N_DIM / 32), 256>>>();
    // 5) m2T[b] = ae ⊙ (WhT[b] @ HT^T) : M=HD=512, N=E, K=N_DIM
    tgemm<1><<<dim3(E_DIM / 128, HD / 128, BATCH), 128, SMEM_SZ>>>(
        pWhT, pHT, pm2T, N_DIM, N_DIM, N_DIM, E_DIM,
        (long)HD * N_DIM, 0, (long)HD * E_DIM, paeT);
    // 6) out[b] = Hr @ m2T[b]^T : M=N_DIM, N=HD, K=E
    tgemm<2><<<dim3(HD / 128, N_DIM / 128, BATCH), 128, SMEM_SZ>>>(
        pHr, pm2T, out, E_DIM, E_DIM, E_DIM, HD,
        0, (long)HD * E_DIM, (long)N_DIM * HD, nullptr);
}